// round 4
// baseline (speedup 1.0000x reference)
#include <cuda_runtime.h>

#define ND 128
#define HID 16
#define N_MAX 100000

typedef unsigned long long u64;

// Scratch (device globals; statically zero-initialized; every run restores
// its own state so graph replays see identical initial conditions)
__device__ __align__(16) int   g_degi[N_MAX];    // int degree counts (reset by rcp_kernel)
__device__ __align__(16) float g_invdeg[N_MAX];  // 1/deg
__device__ __align__(16) float g_s[N_MAX];       // s[m] = tanh3(x_m)·Wc
__device__ float    g_acc;                       // reset by last edge_dot block
__device__ unsigned g_done;                      // wraps to 0 via atomicInc

#define FMA2(d, a, b) \
    asm("fma.rn.f32x2 %0, %1, %2, %3;" : "=l"(d) : "l"(a), "l"(b), "l"(d))
#define PACK2(d, s) \
    asm("mov.b64 %0, {%1, %1};" : "=l"(d) : "r"(__float_as_uint(s)))
#define UNPACK2(lo, hi, s) \
    asm("mov.b64 {%0, %1}, %2;" : "=r"(lo), "=r"(hi) : "l"(s))

__device__ __forceinline__ float ftanh(float v) {
    return 1.0f - __fdividef(2.0f, __expf(2.0f * v) + 1.0f);
}

// ---------------- K1: fused MLP->s (blocks [0,nMlp)) + int deg scatter ----
#define TPB 256
#define MLP_NPT 2
#define DEG_EPT 4

__global__ void __launch_bounds__(TPB) fused1_kernel(
    const float* __restrict__ x,
    const float* __restrict__ W1, const float* __restrict__ b1,
    const float* __restrict__ W2, const float* __restrict__ b2,
    const float* __restrict__ W3, const float* __restrict__ b3,
    const float* __restrict__ Wc,
    const int* __restrict__ esrc,
    int n, int e, int nMlpBlocks)
{
    __shared__ float4 sW1[ND * HID / 4];   // 8KB
    __shared__ float4 sW2[HID * HID / 4];
    __shared__ float4 sW3[HID * HID / 4];
    __shared__ u64 sb1[8], sb2[8], sb3[8];
    __shared__ float sWc[HID];

    int tid = threadIdx.x;

    if (blockIdx.x >= nMlpBlocks) {
        // ---- degree scatter path (int RED) ----
        int db = blockIdx.x - nMlpBlocks;
        int base = (db * TPB + tid) * DEG_EPT;
        if (base + DEG_EPT <= e) {
            int4 s4 = *(const int4*)(esrc + base);
            atomicAdd(&g_degi[s4.x], 1);
            atomicAdd(&g_degi[s4.y], 1);
            atomicAdd(&g_degi[s4.z], 1);
            atomicAdd(&g_degi[s4.w], 1);
        } else {
            for (int i = base; i < e; i++) atomicAdd(&g_degi[esrc[i]], 1);
        }
        return;
    }

    // ---- MLP path ----
    for (int i = tid; i < ND * HID / 4; i += TPB) sW1[i] = ((const float4*)W1)[i];
    if (tid < HID * HID / 4) {
        sW2[tid] = ((const float4*)W2)[tid];
        sW3[tid] = ((const float4*)W3)[tid];
    }
    if (tid < 8) {
        sb1[tid] = ((const u64*)b1)[tid];
        sb2[tid] = ((const u64*)b2)[tid];
        sb3[tid] = ((const u64*)b3)[tid];
    }
    if (tid < HID) sWc[tid] = Wc[tid];
    __syncthreads();

    int node0 = blockIdx.x * (TPB * MLP_NPT) + tid;
    int node1 = node0 + TPB;
    int c0 = min(node0, n - 1);
    int c1 = min(node1, n - 1);

    const float4* xr0 = (const float4*)(x + (size_t)c0 * ND);
    const float4* xr1 = (const float4*)(x + (size_t)c1 * ND);

    u64 h0[8], h1v[8];
#pragma unroll
    for (int q = 0; q < 8; q++) { h0[q] = sb1[q]; h1v[q] = sb1[q]; }

    // layer 1: 128 -> 16, f32x2 packed, 2 nodes/thread
#pragma unroll 4
    for (int k4 = 0; k4 < ND / 4; k4++) {
        float4 xa = xr0[k4];
        float4 xb = xr1[k4];
        float xas[4] = {xa.x, xa.y, xa.z, xa.w};
        float xbs[4] = {xb.x, xb.y, xb.z, xb.w};
#pragma unroll
        for (int i = 0; i < 4; i++) {
            const ulonglong2* wr = (const ulonglong2*)(sW1 + (k4 * 4 + i) * 4);
            u64 xpa, xpb;
            PACK2(xpa, xas[i]);
            PACK2(xpb, xbs[i]);
#pragma unroll
            for (int q = 0; q < 4; q++) {
                ulonglong2 ww = wr[q];
                FMA2(h0[2 * q],      xpa, ww.x);
                FMA2(h0[2 * q + 1],  xpa, ww.y);
                FMA2(h1v[2 * q],     xpb, ww.x);
                FMA2(h1v[2 * q + 1], xpb, ww.y);
            }
        }
    }

    float t0[HID], t1[HID];
#pragma unroll
    for (int q = 0; q < 8; q++) {
        unsigned lo, hi;
        UNPACK2(lo, hi, h0[q]);
        t0[2 * q] = ftanh(__uint_as_float(lo));
        t0[2 * q + 1] = ftanh(__uint_as_float(hi));
        UNPACK2(lo, hi, h1v[q]);
        t1[2 * q] = ftanh(__uint_as_float(lo));
        t1[2 * q + 1] = ftanh(__uint_as_float(hi));
    }

    // layer 2
    u64 a0[8], a1[8];
#pragma unroll
    for (int q = 0; q < 8; q++) { a0[q] = sb2[q]; a1[q] = sb2[q]; }
#pragma unroll
    for (int i = 0; i < HID; i++) {
        const ulonglong2* wr = (const ulonglong2*)(sW2 + i * 4);
        u64 p0, p1;
        PACK2(p0, t0[i]);
        PACK2(p1, t1[i]);
#pragma unroll
        for (int q = 0; q < 4; q++) {
            ulonglong2 ww = wr[q];
            FMA2(a0[2 * q],     p0, ww.x);
            FMA2(a0[2 * q + 1], p0, ww.y);
            FMA2(a1[2 * q],     p1, ww.x);
            FMA2(a1[2 * q + 1], p1, ww.y);
        }
    }
#pragma unroll
    for (int q = 0; q < 8; q++) {
        unsigned lo, hi;
        UNPACK2(lo, hi, a0[q]);
        t0[2 * q] = ftanh(__uint_as_float(lo));
        t0[2 * q + 1] = ftanh(__uint_as_float(hi));
        UNPACK2(lo, hi, a1[q]);
        t1[2 * q] = ftanh(__uint_as_float(lo));
        t1[2 * q + 1] = ftanh(__uint_as_float(hi));
    }

    // layer 3
#pragma unroll
    for (int q = 0; q < 8; q++) { a0[q] = sb3[q]; a1[q] = sb3[q]; }
#pragma unroll
    for (int i = 0; i < HID; i++) {
        const ulonglong2* wr = (const ulonglong2*)(sW3 + i * 4);
        u64 p0, p1;
        PACK2(p0, t0[i]);
        PACK2(p1, t1[i]);
#pragma unroll
        for (int q = 0; q < 4; q++) {
            ulonglong2 ww = wr[q];
            FMA2(a0[2 * q],     p0, ww.x);
            FMA2(a0[2 * q + 1], p0, ww.y);
            FMA2(a1[2 * q],     p1, ww.x);
            FMA2(a1[2 * q + 1], p1, ww.y);
        }
    }

    // tanh + contract with Wc -> scalar per node
    float s0 = 0.f, s1 = 0.f;
#pragma unroll
    for (int q = 0; q < 8; q++) {
        unsigned lo, hi;
        UNPACK2(lo, hi, a0[q]);
        s0 += ftanh(__uint_as_float(lo)) * sWc[2 * q];
        s0 += ftanh(__uint_as_float(hi)) * sWc[2 * q + 1];
        UNPACK2(lo, hi, a1[q]);
        s1 += ftanh(__uint_as_float(lo)) * sWc[2 * q];
        s1 += ftanh(__uint_as_float(hi)) * sWc[2 * q + 1];
    }

    // duplicate clamped writes carry identical values -> benign
    g_s[c0] = s0;
    g_s[c1] = s1;
}

// ---------------- K2: invdeg = 1/deg, and reset deg counters --------------
__global__ void rcp_kernel(int n) {
    int i = blockIdx.x * blockDim.x + threadIdx.x;
    if (i < n) {
        int d = g_degi[i];
        g_invdeg[i] = __frcp_rn((float)d);  // inf for d==0, never read (src has deg>=1)
        g_degi[i] = 0;                       // restore for next graph replay
    }
}

// ---------------- K3: edge dot + fused final sigmoid ----------------------
#define E_TPB 256
#define E_EPT 8

__global__ void __launch_bounds__(E_TPB) edge_dot_kernel(
    const int* __restrict__ src, const int* __restrict__ dst,
    const float* __restrict__ bc, float* __restrict__ out,
    int e, float inv_n)
{
    __shared__ float sRed[E_TPB / 32];
    int tid = threadIdx.x;
    int base = (blockIdx.x * E_TPB + tid) * E_EPT;
    float acc = 0.f;

    if (base + E_EPT <= e) {
        int4 sa = *(const int4*)(src + base);
        int4 sb = *(const int4*)(src + base + 4);
        int4 da = *(const int4*)(dst + base);
        int4 db = *(const int4*)(dst + base + 4);
        float w0 = __ldg(&g_invdeg[sa.x]), w1 = __ldg(&g_invdeg[sa.y]);
        float w2 = __ldg(&g_invdeg[sa.z]), w3 = __ldg(&g_invdeg[sa.w]);
        float w4 = __ldg(&g_invdeg[sb.x]), w5 = __ldg(&g_invdeg[sb.y]);
        float w6 = __ldg(&g_invdeg[sb.z]), w7 = __ldg(&g_invdeg[sb.w]);
        float v0 = __ldg(&g_s[da.x]), v1 = __ldg(&g_s[da.y]);
        float v2 = __ldg(&g_s[da.z]), v3 = __ldg(&g_s[da.w]);
        float v4 = __ldg(&g_s[db.x]), v5 = __ldg(&g_s[db.y]);
        float v6 = __ldg(&g_s[db.z]), v7 = __ldg(&g_s[db.w]);
        acc = fmaf(v0, w0, acc); acc = fmaf(v1, w1, acc);
        acc = fmaf(v2, w2, acc); acc = fmaf(v3, w3, acc);
        acc = fmaf(v4, w4, acc); acc = fmaf(v5, w5, acc);
        acc = fmaf(v6, w6, acc); acc = fmaf(v7, w7, acc);
    } else {
        for (int i = base; i < e; i++)
            acc += __ldg(&g_s[dst[i]]) * __ldg(&g_invdeg[src[i]]);
    }

    // warp + block reduce, one atomic per block
    unsigned m = 0xffffffffu;
#pragma unroll
    for (int off = 16; off > 0; off >>= 1)
        acc += __shfl_down_sync(m, acc, off);
    if ((tid & 31) == 0) sRed[tid >> 5] = acc;
    __syncthreads();

    if (tid == 0) {
        float v = 0.f;
#pragma unroll
        for (int wq = 0; wq < E_TPB / 32; wq++) v += sRed[wq];
        atomicAdd(&g_acc, v);
        __threadfence();
        unsigned ticket = atomicInc(&g_done, gridDim.x - 1);  // wraps to 0 on last
        if (ticket == gridDim.x - 1) {
            // last block: all g_acc contributions are globally visible
            float z = g_acc * inv_n + bc[0];
            out[0] = 1.0f / (1.0f + __expf(-z));
            g_acc = 0.f;  // restore for next graph replay
        }
    }
}

extern "C" void kernel_launch(void* const* d_in, const int* in_sizes, int n_in,
                              void* d_out, int out_size) {
    const float* x    = (const float*)d_in[0];
    const int*   esrc = (const int*)  d_in[1];
    const int*   edst = (const int*)  d_in[2];
    const float* W1   = (const float*)d_in[3];
    const float* b1   = (const float*)d_in[4];
    const float* W2   = (const float*)d_in[5];
    const float* b2   = (const float*)d_in[6];
    const float* W3   = (const float*)d_in[7];
    const float* b3   = (const float*)d_in[8];
    const float* Wc   = (const float*)d_in[9];
    const float* bc   = (const float*)d_in[10];
    float* out = (float*)d_out;

    int n = in_sizes[0] / ND;
    int e = in_sizes[1];
    if (n > N_MAX) n = N_MAX;

    int nMlp = (n + TPB * MLP_NPT - 1) / (TPB * MLP_NPT);
    int nDeg = (e + TPB * DEG_EPT - 1) / (TPB * DEG_EPT);
    fused1_kernel<<<nMlp + nDeg, TPB>>>(x, W1, b1, W2, b2, W3, b3, Wc, esrc, n, e, nMlp);

    rcp_kernel<<<(n + 255) / 256, 256>>>(n);

    int nEdge = (e + E_TPB * E_EPT - 1) / (E_TPB * E_EPT);
    edge_dot_kernel<<<nEdge, E_TPB>>>(esrc, edst, bc, out, e, 1.0f / (float)n);
}